// round 9
// baseline (speedup 1.0000x reference)
#include <cuda_runtime.h>
#include <cuda_fp16.h>

#define BB 256
#define LL 32
#define RRR 2592
#define BL 8192           // BB*LL
#define RL 82944          // RR*LL
#define RCH 18            // r-chunk for s-kernels
#define GY  144           // RRR/RCH
#define UHAT_ELEMS (RRR*BB*LL)

// Scratch (device globals: no allocation in kernel_launch)
__device__ __half g_uhat[UHAT_ELEMS];  // layout [r][b][l], fp16, 42.5 MB
__device__ float g_s0[BL];
__device__ float g_s1[BL];
__device__ float g_s2[BL];
__device__ float g_a0[RRR];
__device__ float g_a1[RRR];

// squash(s) = s^2*s / ((1+s^2)*sqrt(s^2)) = s*|s| / (1+s^2)
__device__ __forceinline__ float squashf(float s) {
    return __fdividef(s * fabsf(s), 1.0f + s * s);
}

// ---------------------------------------------------------------------------
// u_hat[r,b,l] = sum_c W[r,l,c] * x[b,r,c]; one block per r. fp16 store.
// Blocks 0/1 also re-init scratch for this graph replay.
__global__ __launch_bounds__(256) void k_uhat(const float* __restrict__ x,
                                              const float* __restrict__ W) {
    __shared__ float4 xs4[BB * 4];      // x[:, r, :] as float4 rows, 16 KB
    __shared__ float  Ws[32 * 17];
    const int r = blockIdx.x;
    const int t = threadIdx.x;

    if (r == 0) {
        #pragma unroll
        for (int k = 0; k < 32; k++) {
            g_s0[t + k * 256] = 0.0f;
            g_s1[t + k * 256] = 0.0f;
            g_s2[t + k * 256] = 0.0f;
        }
    } else if (r == 1) {
        for (int i = t; i < RRR; i += 256) g_a1[i] = 0.0f;
    }

    for (int i = t; i < 512; i += 256) {
        int l = i >> 4, c = i & 15;
        Ws[l * 17 + c] = W[r * 512 + i];
    }
    const float4* x4 = (const float4*)x;
    #pragma unroll
    for (int k = 0; k < 4; k++) {
        int idx = k * 256 + t;           // idx = b*4 + c4
        int b = idx >> 2, c4 = idx & 3;
        xs4[idx] = x4[(b * RRR + r) * 4 + c4];
    }
    __syncthreads();

    const int lane = t & 31, warp = t >> 5;
    float w[16];
    #pragma unroll
    for (int c = 0; c < 16; c++) w[c] = Ws[lane * 17 + c];

    #pragma unroll 4
    for (int it = 0; it < 32; it++) {
        int b = it * 8 + warp;
        float4 xa = xs4[b * 4 + 0];
        float4 xb = xs4[b * 4 + 1];
        float4 xc = xs4[b * 4 + 2];
        float4 xd = xs4[b * 4 + 3];
        float acc = w[0] * xa.x;
        acc = fmaf(w[1],  xa.y, acc);  acc = fmaf(w[2],  xa.z, acc);
        acc = fmaf(w[3],  xa.w, acc);  acc = fmaf(w[4],  xb.x, acc);
        acc = fmaf(w[5],  xb.y, acc);  acc = fmaf(w[6],  xb.z, acc);
        acc = fmaf(w[7],  xb.w, acc);  acc = fmaf(w[8],  xc.x, acc);
        acc = fmaf(w[9],  xc.y, acc);  acc = fmaf(w[10], xc.z, acc);
        acc = fmaf(w[11], xc.w, acc);  acc = fmaf(w[12], xd.x, acc);
        acc = fmaf(w[13], xd.y, acc);  acc = fmaf(w[14], xd.z, acc);
        acc = fmaf(w[15], xd.w, acc);
        g_uhat[(size_t)r * BL + b * LL + lane] = __float2half_rn(acc);
    }
}

// ---------------------------------------------------------------------------
// Per-block softmax over (g_a0 + g_a1): fills cs[0..RCH) for chunk r0.
// All blocks compute identical reductions (deterministic).
__device__ __forceinline__ void block_softmax(float* cs, int r0, int t) {
    __shared__ float red[8];
    const int w = t >> 5, lane = t & 31;
    float mx = -1e30f;
    for (int i = t; i < RRR; i += 256)
        mx = fmaxf(mx, g_a0[i] + g_a1[i]);
    #pragma unroll
    for (int o = 16; o; o >>= 1) mx = fmaxf(mx, __shfl_xor_sync(0xffffffffu, mx, o));
    if (lane == 0) red[w] = mx;
    __syncthreads();
    mx = red[0];
    #pragma unroll
    for (int j = 1; j < 8; j++) mx = fmaxf(mx, red[j]);
    __syncthreads();

    float es = 0.0f;
    for (int i = t; i < RRR; i += 256)
        es += __expf(g_a0[i] + g_a1[i] - mx);
    #pragma unroll
    for (int o = 16; o; o >>= 1) es += __shfl_xor_sync(0xffffffffu, es, o);
    if (lane == 0) red[w] = es;
    __syncthreads();
    es = red[0];
    #pragma unroll
    for (int j = 1; j < 8; j++) es += red[j];
    const float inv = 1.0f / es;
    if (t < RCH) cs[t] = __expf(g_a0[r0 + t] + g_a1[r0 + t] - mx) * inv;
    __syncthreads();
}

// ---------------------------------------------------------------------------
// Core s-accumulation: sbuf[b,l] += sum_{i<RCH} cs[i]*u_hat[r0+i,b,l].
// Warp loads 512B contiguous per r (int4/lane over 8 b-rows).
__device__ __forceinline__ void s_accum(const float* cs, int r0, int bx, int t,
                                        float* sbuf) {
    const int w = t >> 5, lane = t & 31;
    const int b = bx * 64 + w * 8 + (lane >> 2);
    const int l8 = (lane & 3) * 8;
    const int4* u = (const int4*)g_uhat + (size_t)r0 * 1024 + b * 4 + (lane & 3);

    float a[8] = {0.f, 0.f, 0.f, 0.f, 0.f, 0.f, 0.f, 0.f};
    #pragma unroll 6
    for (int i = 0; i < RCH; i++) {
        int4 p = u[(size_t)i * 1024];
        const float cr = cs[i];
        const __half2* hp = (const __half2*)&p;
        #pragma unroll
        for (int j = 0; j < 4; j++) {
            float2 f = __half22float2(hp[j]);
            a[2 * j]     = fmaf(cr, f.x, a[2 * j]);
            a[2 * j + 1] = fmaf(cr, f.y, a[2 * j + 1]);
        }
    }
    float* sdst = sbuf + b * LL + l8;
    #pragma unroll
    for (int j = 0; j < 8; j++) atomicAdd(sdst + j, a[j]);
}

// it0: c uniform = 1/RRR — no softmax needed.
__global__ __launch_bounds__(256) void k_s0() {
    __shared__ float cs[RCH];
    const int t = threadIdx.x;
    if (t < RCH) cs[t] = 1.0f / (float)RRR;
    __syncthreads();
    s_accum(cs, blockIdx.y * RCH, blockIdx.x, t, g_s0);
}

// it1: c = softmax(a0)  (g_a1 is zero here)
__global__ __launch_bounds__(256) void k_s1() {
    __shared__ float cs[RCH];
    const int t = threadIdx.x;
    const int r0 = blockIdx.y * RCH;
    block_softmax(cs, r0, t);
    s_accum(cs, r0, blockIdx.x, t, g_s1);
}

// ---------------------------------------------------------------------------
// a[r] = mean_b sum_l u_hat[r,b,l]*squash(s)[b,l]; 4 r's per block, grid 648.
template<int IT>
__global__ __launch_bounds__(256) void k_a() {
    __shared__ float vsm[BL];          // squash(s), 32 KB
    __shared__ float red[4][9];
    const int t = threadIdx.x;
    const int w = t >> 5, lane = t & 31;
    const float* sbuf = (IT == 0) ? g_s0 : g_s1;
    float* abuf = (IT == 0) ? g_a0 : g_a1;

    const float4* s4 = (const float4*)sbuf;
    float4* v4 = (float4*)vsm;
    for (int i = t; i < BL / 4; i += 256) {
        float4 s = s4[i];
        float4 o;
        o.x = squashf(s.x); o.y = squashf(s.y);
        o.z = squashf(s.z); o.w = squashf(s.w);
        v4[i] = o;
    }
    __syncthreads();

    const int rbase = blockIdx.x * 4;
    for (int rr = 0; rr < 4; rr++) {
        const int4* u = (const int4*)g_uhat + (size_t)(rbase + rr) * 1024;
        float a[8] = {0.f, 0.f, 0.f, 0.f, 0.f, 0.f, 0.f, 0.f};
        #pragma unroll
        for (int j = 0; j < 4; j++) {
            int idx = j * 256 + t;
            int4 p = u[idx];
            const __half2* hp = (const __half2*)&p;
            float4 va = v4[idx * 2];
            float4 vb = v4[idx * 2 + 1];
            float2 f0 = __half22float2(hp[0]);
            float2 f1 = __half22float2(hp[1]);
            float2 f2 = __half22float2(hp[2]);
            float2 f3 = __half22float2(hp[3]);
            a[0] = fmaf(f0.x, va.x, a[0]);  a[1] = fmaf(f0.y, va.y, a[1]);
            a[2] = fmaf(f1.x, va.z, a[2]);  a[3] = fmaf(f1.y, va.w, a[3]);
            a[4] = fmaf(f2.x, vb.x, a[4]);  a[5] = fmaf(f2.y, vb.y, a[5]);
            a[6] = fmaf(f3.x, vb.z, a[6]);  a[7] = fmaf(f3.y, vb.w, a[7]);
        }
        float s = ((a[0] + a[1]) + (a[2] + a[3])) + ((a[4] + a[5]) + (a[6] + a[7]));
        #pragma unroll
        for (int o = 16; o; o >>= 1) s += __shfl_xor_sync(0xffffffffu, s, o);
        if (lane == 0) red[rr][w] = s;
    }
    __syncthreads();
    if (t < 32) {
        int rr = t >> 3, ww = t & 7;
        float v = red[rr][ww];
        v += __shfl_xor_sync(0xffffffffu, v, 1);
        v += __shfl_xor_sync(0xffffffffu, v, 2);
        v += __shfl_xor_sync(0xffffffffu, v, 4);
        if (ww == 0) abuf[rbase + rr] = v * (1.0f / (float)BB);
    }
}

// ---------------------------------------------------------------------------
// Final iteration fused: c2 = softmax(a0+a1) per block; writes
// u_out[b,r,l] = c2[r]*u_hat[r,b,l] and accumulates s2 via atomics.
__global__ __launch_bounds__(256) void k_s_out(float* __restrict__ out) {
    __shared__ float cs[RCH];
    const int t = threadIdx.x;
    const int r0 = blockIdx.y * RCH;
    block_softmax(cs, r0, t);

    const int w = t >> 5, lane = t & 31;
    const int b = blockIdx.x * 64 + w * 8 + (lane >> 2);
    const int l8 = (lane & 3) * 8;
    const int4* u = (const int4*)g_uhat + (size_t)r0 * 1024 + b * 4 + (lane & 3);
    float* uo = out + BL + b * RL + l8;

    float a[8] = {0.f, 0.f, 0.f, 0.f, 0.f, 0.f, 0.f, 0.f};
    #pragma unroll 6
    for (int i = 0; i < RCH; i++) {
        int4 p = u[(size_t)i * 1024];
        const float cr = cs[i];
        const __half2* hp = (const __half2*)&p;
        float2 f0 = __half22float2(hp[0]);
        float2 f1 = __half22float2(hp[1]);
        float2 f2 = __half22float2(hp[2]);
        float2 f3 = __half22float2(hp[3]);
        float4 o1, o2;
        o1.x = cr * f0.x;  o1.y = cr * f0.y;
        o1.z = cr * f1.x;  o1.w = cr * f1.y;
        o2.x = cr * f2.x;  o2.y = cr * f2.y;
        o2.z = cr * f3.x;  o2.w = cr * f3.y;
        a[0] += o1.x; a[1] += o1.y; a[2] += o1.z; a[3] += o1.w;
        a[4] += o2.x; a[5] += o2.y; a[6] += o2.z; a[7] += o2.w;
        float* dst = uo + (r0 + i) * LL;
        ((float4*)dst)[0] = o1;
        ((float4*)dst)[1] = o2;
    }
    float* sdst = g_s2 + b * LL + l8;
    #pragma unroll
    for (int j = 0; j < 8; j++) atomicAdd(sdst + j, a[j]);
}

// ---------------------------------------------------------------------------
// v_out = squash(s2) into out[0:8192].
__global__ __launch_bounds__(256) void k_vout(float* __restrict__ out) {
    int i = blockIdx.x * 256 + threadIdx.x;
    out[i] = squashf(g_s2[i]);
}

// ---------------------------------------------------------------------------
extern "C" void kernel_launch(void* const* d_in, const int* in_sizes, int n_in,
                              void* d_out, int out_size) {
    const float* x = (const float*)d_in[0];   // (B, R, C)
    const float* W = (const float*)d_in[1];   // (1, R, 1, L, C)
    float* out = (float*)d_out;

    k_uhat<<<RRR, 256>>>(x, W);                // + scratch init
    k_s0<<<dim3(4, GY), 256>>>();              // it 0 (uniform c)
    k_a<0><<<648, 256>>>();                    // a0
    k_s1<<<dim3(4, GY), 256>>>();              // it 1 (softmax in-block)
    k_a<1><<<648, 256>>>();                    // a1
    k_s_out<<<dim3(4, GY), 256>>>(out);        // it 2 + u_out
    k_vout<<<32, 256>>>(out);                  // v_out
}

// round 10
// speedup vs baseline: 1.4815x; 1.4815x over previous
#include <cuda_runtime.h>
#include <cuda_fp16.h>

#define BB 256
#define LL 32
#define RRR 2592
#define BL 8192           // BB*LL
#define RL 82944          // RRR*LL
#define RCH 144           // r-chunk per block in s-kernels
#define GYS 18            // RRR/RCH
#define WRD 18            // r's per warp (RCH/8)
#define UHAT_ELEMS (RRR*BB*LL)

// Scratch (device globals: no allocation in kernel_launch)
__device__ __half g_uhat[UHAT_ELEMS];  // layout [r][b][l], fp16, 42.5 MB
__device__ float g_s0[BL];
__device__ float g_s1[BL];
__device__ float g_s2[BL];
__device__ float g_a0[RRR];
__device__ float g_a1[RRR];

// squash(s) = s^2*s / ((1+s^2)*sqrt(s^2)) = s*|s| / (1+s^2)
__device__ __forceinline__ float squashf(float s) {
    return __fdividef(s * fabsf(s), 1.0f + s * s);
}

// ---------------------------------------------------------------------------
// u_hat[r,b,l] = sum_c W[r,l,c] * x[b,r,c]; one block per r. fp16 store.
// Blocks 0/1 also re-init scratch for this graph replay.
__global__ __launch_bounds__(256) void k_uhat(const float* __restrict__ x,
                                              const float* __restrict__ W) {
    __shared__ float4 xs4[BB * 4];      // x[:, r, :] as float4 rows, 16 KB
    __shared__ float  Ws[32 * 17];
    const int r = blockIdx.x;
    const int t = threadIdx.x;

    if (r == 0) {
        #pragma unroll
        for (int k = 0; k < 32; k++) {
            g_s0[t + k * 256] = 0.0f;
            g_s1[t + k * 256] = 0.0f;
            g_s2[t + k * 256] = 0.0f;
        }
    } else if (r == 1) {
        for (int i = t; i < RRR; i += 256) g_a1[i] = 0.0f;
    }

    for (int i = t; i < 512; i += 256) {
        int l = i >> 4, c = i & 15;
        Ws[l * 17 + c] = W[r * 512 + i];
    }
    const float4* x4 = (const float4*)x;
    #pragma unroll
    for (int k = 0; k < 4; k++) {
        int idx = k * 256 + t;           // idx = b*4 + c4
        int b = idx >> 2, c4 = idx & 3;
        xs4[idx] = x4[(b * RRR + r) * 4 + c4];
    }
    __syncthreads();

    const int lane = t & 31, warp = t >> 5;
    float w[16];
    #pragma unroll
    for (int c = 0; c < 16; c++) w[c] = Ws[lane * 17 + c];

    #pragma unroll 4
    for (int it = 0; it < 32; it++) {
        int b = it * 8 + warp;
        float4 xa = xs4[b * 4 + 0];
        float4 xb = xs4[b * 4 + 1];
        float4 xc = xs4[b * 4 + 2];
        float4 xd = xs4[b * 4 + 3];
        float acc = w[0] * xa.x;
        acc = fmaf(w[1],  xa.y, acc);  acc = fmaf(w[2],  xa.z, acc);
        acc = fmaf(w[3],  xa.w, acc);  acc = fmaf(w[4],  xb.x, acc);
        acc = fmaf(w[5],  xb.y, acc);  acc = fmaf(w[6],  xb.z, acc);
        acc = fmaf(w[7],  xb.w, acc);  acc = fmaf(w[8],  xc.x, acc);
        acc = fmaf(w[9],  xc.y, acc);  acc = fmaf(w[10], xc.z, acc);
        acc = fmaf(w[11], xc.w, acc);  acc = fmaf(w[12], xd.x, acc);
        acc = fmaf(w[13], xd.y, acc);  acc = fmaf(w[14], xd.z, acc);
        acc = fmaf(w[15], xd.w, acc);
        g_uhat[(size_t)r * BL + b * LL + lane] = __float2half_rn(acc);
    }
}

// ---------------------------------------------------------------------------
// Per-block softmax over (g_a0 + g_a1): fills cs[0..RCH) for chunk r0.
__device__ __forceinline__ void block_softmax(float* cs, int r0, int t) {
    __shared__ float red[8];
    const int w = t >> 5, lane = t & 31;
    float mx = -1e30f;
    for (int i = t; i < RRR; i += 256)
        mx = fmaxf(mx, g_a0[i] + g_a1[i]);
    #pragma unroll
    for (int o = 16; o; o >>= 1) mx = fmaxf(mx, __shfl_xor_sync(0xffffffffu, mx, o));
    if (lane == 0) red[w] = mx;
    __syncthreads();
    mx = red[0];
    #pragma unroll
    for (int j = 1; j < 8; j++) mx = fmaxf(mx, red[j]);
    __syncthreads();

    float es = 0.0f;
    for (int i = t; i < RRR; i += 256)
        es += __expf(g_a0[i] + g_a1[i] - mx);
    #pragma unroll
    for (int o = 16; o; o >>= 1) es += __shfl_xor_sync(0xffffffffu, es, o);
    if (lane == 0) red[w] = es;
    __syncthreads();
    es = red[0];
    #pragma unroll
    for (int j = 1; j < 8; j++) es += red[j];
    const float inv = 1.0f / es;
    for (int i = t; i < RCH; i += 256)
        cs[i] = __expf(g_a0[r0 + i] + g_a1[r0 + i] - mx) * inv;
    __syncthreads();
}

// ---------------------------------------------------------------------------
// Cross-warp reduce of per-warp partials (a[8] each) + 256 global REDs.
// Flat tile index f = lane*8+j : b = b0 + (f>>5), l = ((f>>3)&3)*8 + (f&7).
__device__ __forceinline__ void s_reduce_store(const float* a, int b0, int t,
                                               float* sbuf, float scale) {
    __shared__ float sm[8][256];
    const int w = t >> 5, lane = t & 31;
    #pragma unroll
    for (int j = 0; j < 8; j++) sm[w][lane * 8 + j] = a[j];
    __syncthreads();
    float v = sm[0][t];
    #pragma unroll
    for (int ww = 1; ww < 8; ww++) v += sm[ww][t];
    const int b = b0 + (t >> 5);
    const int l = ((t >> 3) & 3) * 8 + (t & 7);
    atomicAdd(&sbuf[b * LL + l], v * scale);
}

// Per-warp streaming accumulate: warp covers same 8-b window, r in
// [r0 + w*WRD, +WRD). cs==nullptr -> uniform weights (sum only).
__device__ __forceinline__ void s_warp_accum(float* a, const float* cs,
                                             int r0, int b0, int t) {
    const int w = t >> 5, lane = t & 31;
    const int rw = r0 + w * WRD;
    const int b = b0 + (lane >> 2);
    const int4* u = (const int4*)g_uhat + (size_t)rw * 1024 + b * 4 + (lane & 3);

    #pragma unroll
    for (int j = 0; j < 8; j++) a[j] = 0.0f;
    #pragma unroll 6
    for (int i = 0; i < WRD; i++) {
        int4 p = u[(size_t)i * 1024];
        const float cr = cs ? cs[w * WRD + i] : 1.0f;
        const __half2* hp = (const __half2*)&p;
        #pragma unroll
        for (int j = 0; j < 4; j++) {
            float2 f = __half22float2(hp[j]);
            if (cs) {
                a[2 * j]     = fmaf(cr, f.x, a[2 * j]);
                a[2 * j + 1] = fmaf(cr, f.y, a[2 * j + 1]);
            } else {
                a[2 * j]     += f.x;
                a[2 * j + 1] += f.y;
            }
        }
    }
}

// it0: c uniform = 1/RRR.
__global__ __launch_bounds__(256) void k_s0() {
    const int t = threadIdx.x;
    float a[8];
    s_warp_accum(a, nullptr, blockIdx.y * RCH, blockIdx.x * 8, t);
    s_reduce_store(a, blockIdx.x * 8, t, g_s0, 1.0f / (float)RRR);
}

// it1: c = softmax(a0)  (g_a1 is zero here)
__global__ __launch_bounds__(256) void k_s1() {
    __shared__ float cs[RCH];
    const int t = threadIdx.x;
    const int r0 = blockIdx.y * RCH;
    block_softmax(cs, r0, t);
    float a[8];
    s_warp_accum(a, cs, r0, blockIdx.x * 8, t);
    s_reduce_store(a, blockIdx.x * 8, t, g_s1, 1.0f);
}

// ---------------------------------------------------------------------------
// a[r] = mean_b sum_l u_hat[r,b,l]*squash(s)[b,l]; 4 r's per block, grid 648.
template<int IT>
__global__ __launch_bounds__(256) void k_a() {
    __shared__ float vsm[BL];          // squash(s), 32 KB
    __shared__ float red[4][9];
    const int t = threadIdx.x;
    const int w = t >> 5, lane = t & 31;
    const float* sbuf = (IT == 0) ? g_s0 : g_s1;
    float* abuf = (IT == 0) ? g_a0 : g_a1;

    const float4* s4 = (const float4*)sbuf;
    float4* v4 = (float4*)vsm;
    for (int i = t; i < BL / 4; i += 256) {
        float4 s = s4[i];
        float4 o;
        o.x = squashf(s.x); o.y = squashf(s.y);
        o.z = squashf(s.z); o.w = squashf(s.w);
        v4[i] = o;
    }
    __syncthreads();

    const int rbase = blockIdx.x * 4;
    for (int rr = 0; rr < 4; rr++) {
        const int4* u = (const int4*)g_uhat + (size_t)(rbase + rr) * 1024;
        float a[8] = {0.f, 0.f, 0.f, 0.f, 0.f, 0.f, 0.f, 0.f};
        #pragma unroll
        for (int j = 0; j < 4; j++) {
            int idx = j * 256 + t;
            int4 p = u[idx];
            const __half2* hp = (const __half2*)&p;
            float4 va = v4[idx * 2];
            float4 vb = v4[idx * 2 + 1];
            float2 f0 = __half22float2(hp[0]);
            float2 f1 = __half22float2(hp[1]);
            float2 f2 = __half22float2(hp[2]);
            float2 f3 = __half22float2(hp[3]);
            a[0] = fmaf(f0.x, va.x, a[0]);  a[1] = fmaf(f0.y, va.y, a[1]);
            a[2] = fmaf(f1.x, va.z, a[2]);  a[3] = fmaf(f1.y, va.w, a[3]);
            a[4] = fmaf(f2.x, vb.x, a[4]);  a[5] = fmaf(f2.y, vb.y, a[5]);
            a[6] = fmaf(f3.x, vb.z, a[6]);  a[7] = fmaf(f3.y, vb.w, a[7]);
        }
        float s = ((a[0] + a[1]) + (a[2] + a[3])) + ((a[4] + a[5]) + (a[6] + a[7]));
        #pragma unroll
        for (int o = 16; o; o >>= 1) s += __shfl_xor_sync(0xffffffffu, s, o);
        if (lane == 0) red[rr][w] = s;
    }
    __syncthreads();
    if (t < 32) {
        int rr = t >> 3, ww = t & 7;
        float v = red[rr][ww];
        v += __shfl_xor_sync(0xffffffffu, v, 1);
        v += __shfl_xor_sync(0xffffffffu, v, 2);
        v += __shfl_xor_sync(0xffffffffu, v, 4);
        if (ww == 0) abuf[rbase + rr] = v * (1.0f / (float)BB);
    }
}

// ---------------------------------------------------------------------------
// Final iteration fused: c2 = softmax(a0+a1); writes u_out = c2[r]*u_hat and
// accumulates s2 via smem reduction + 256 REDs per block.
__global__ __launch_bounds__(256) void k_s_out(float* __restrict__ out) {
    __shared__ float cs[RCH];
    const int t = threadIdx.x;
    const int r0 = blockIdx.y * RCH;
    const int b0 = blockIdx.x * 8;
    block_softmax(cs, r0, t);

    const int w = t >> 5, lane = t & 31;
    const int rw = r0 + w * WRD;
    const int b = b0 + (lane >> 2);
    const int l8 = (lane & 3) * 8;
    const int4* u = (const int4*)g_uhat + (size_t)rw * 1024 + b * 4 + (lane & 3);
    float* uo = out + BL + b * RL + l8;

    float a[8] = {0.f, 0.f, 0.f, 0.f, 0.f, 0.f, 0.f, 0.f};
    #pragma unroll 6
    for (int i = 0; i < WRD; i++) {
        int4 p = u[(size_t)i * 1024];
        const float cr = cs[w * WRD + i];
        const __half2* hp = (const __half2*)&p;
        float2 f0 = __half22float2(hp[0]);
        float2 f1 = __half22float2(hp[1]);
        float2 f2 = __half22float2(hp[2]);
        float2 f3 = __half22float2(hp[3]);
        float4 o1, o2;
        o1.x = cr * f0.x;  o1.y = cr * f0.y;
        o1.z = cr * f1.x;  o1.w = cr * f1.y;
        o2.x = cr * f2.x;  o2.y = cr * f2.y;
        o2.z = cr * f3.x;  o2.w = cr * f3.y;
        a[0] += o1.x; a[1] += o1.y; a[2] += o1.z; a[3] += o1.w;
        a[4] += o2.x; a[5] += o2.y; a[6] += o2.z; a[7] += o2.w;
        float* dst = uo + (rw + i) * LL;
        ((float4*)dst)[0] = o1;
        ((float4*)dst)[1] = o2;
    }
    s_reduce_store(a, b0, t, g_s2, 1.0f);
}

// ---------------------------------------------------------------------------
// v_out = squash(s2) into out[0:8192].
__global__ __launch_bounds__(256) void k_vout(float* __restrict__ out) {
    int i = blockIdx.x * 256 + threadIdx.x;
    out[i] = squashf(g_s2[i]);
}

// ---------------------------------------------------------------------------
extern "C" void kernel_launch(void* const* d_in, const int* in_sizes, int n_in,
                              void* d_out, int out_size) {
    const float* x = (const float*)d_in[0];   // (B, R, C)
    const float* W = (const float*)d_in[1];   // (1, R, 1, L, C)
    float* out = (float*)d_out;

    k_uhat<<<RRR, 256>>>(x, W);                // + scratch init
    k_s0<<<dim3(32, GYS), 256>>>();            // it 0 (uniform c)
    k_a<0><<<648, 256>>>();                    // a0
    k_s1<<<dim3(32, GYS), 256>>>();            // it 1
    k_a<1><<<648, 256>>>();                    // a1
    k_s_out<<<dim3(32, GYS), 256>>>(out);      // it 2 + u_out
    k_vout<<<32, 256>>>(out);                  // v_out
}

// round 11
// speedup vs baseline: 1.5371x; 1.0375x over previous
#include <cuda_runtime.h>
#include <cuda_fp16.h>

#define BB 256
#define LL 32
#define RRR 2592
#define BL 8192           // BB*LL
#define RL 82944          // RRR*LL
#define RCH 144           // r-chunk per block in s-kernels
#define GYS 18            // RRR/RCH
#define WRD 18            // r's per warp (RCH/8)
#define UHAT_ELEMS (RRR*BB*LL)

// Scratch (device globals: no allocation in kernel_launch)
__device__ __half g_uhat[UHAT_ELEMS];  // layout [r][b][l], fp16, 42.5 MB
__device__ float g_s0[BL];
__device__ float g_s1[BL];
__device__ float g_s2[BL];
__device__ float g_a0[RRR];
__device__ float g_a1[RRR];

// squash(s) = s^2*s / ((1+s^2)*sqrt(s^2)) = s*|s| / (1+s^2)
__device__ __forceinline__ float squashf(float s) {
    return __fdividef(s * fabsf(s), 1.0f + s * s);
}

// ---------------------------------------------------------------------------
// u_hat[r,b,l] = sum_c W[r,l,c] * x[b,r,c]; one block per r. fp16 store.
// Blocks 0/1 also re-init scratch for this graph replay.
__global__ __launch_bounds__(256) void k_uhat(const float* __restrict__ x,
                                              const float* __restrict__ W) {
    __shared__ float4 xs4[BB * 4];      // x[:, r, :] as float4 rows, 16 KB
    __shared__ float  Ws[32 * 17];
    const int r = blockIdx.x;
    const int t = threadIdx.x;

    if (r == 0) {
        #pragma unroll
        for (int k = 0; k < 32; k++) {
            g_s0[t + k * 256] = 0.0f;
            g_s1[t + k * 256] = 0.0f;
            g_s2[t + k * 256] = 0.0f;
        }
    } else if (r == 1) {
        for (int i = t; i < RRR; i += 256) g_a1[i] = 0.0f;
    }

    for (int i = t; i < 512; i += 256) {
        int l = i >> 4, c = i & 15;
        Ws[l * 17 + c] = W[r * 512 + i];
    }
    const float4* x4 = (const float4*)x;
    #pragma unroll
    for (int k = 0; k < 4; k++) {
        int idx = k * 256 + t;           // idx = b*4 + c4
        int b = idx >> 2, c4 = idx & 3;
        xs4[idx] = x4[(b * RRR + r) * 4 + c4];
    }
    __syncthreads();

    const int lane = t & 31, warp = t >> 5;
    float w[16];
    #pragma unroll
    for (int c = 0; c < 16; c++) w[c] = Ws[lane * 17 + c];

    #pragma unroll 4
    for (int it = 0; it < 32; it++) {
        int b = it * 8 + warp;
        float4 xa = xs4[b * 4 + 0];
        float4 xb = xs4[b * 4 + 1];
        float4 xc = xs4[b * 4 + 2];
        float4 xd = xs4[b * 4 + 3];
        float acc = w[0] * xa.x;
        acc = fmaf(w[1],  xa.y, acc);  acc = fmaf(w[2],  xa.z, acc);
        acc = fmaf(w[3],  xa.w, acc);  acc = fmaf(w[4],  xb.x, acc);
        acc = fmaf(w[5],  xb.y, acc);  acc = fmaf(w[6],  xb.z, acc);
        acc = fmaf(w[7],  xb.w, acc);  acc = fmaf(w[8],  xc.x, acc);
        acc = fmaf(w[9],  xc.y, acc);  acc = fmaf(w[10], xc.z, acc);
        acc = fmaf(w[11], xc.w, acc);  acc = fmaf(w[12], xd.x, acc);
        acc = fmaf(w[13], xd.y, acc);  acc = fmaf(w[14], xd.z, acc);
        acc = fmaf(w[15], xd.w, acc);
        g_uhat[(size_t)r * BL + b * LL + lane] = __float2half_rn(acc);
    }
}

// ---------------------------------------------------------------------------
// Per-block softmax over (g_a0 + g_a1): fills cs[0..RCH) for chunk r0.
__device__ __forceinline__ void block_softmax(float* cs, int r0, int t) {
    __shared__ float red[8];
    const int w = t >> 5, lane = t & 31;
    float mx = -1e30f;
    for (int i = t; i < RRR; i += 256)
        mx = fmaxf(mx, g_a0[i] + g_a1[i]);
    #pragma unroll
    for (int o = 16; o; o >>= 1) mx = fmaxf(mx, __shfl_xor_sync(0xffffffffu, mx, o));
    if (lane == 0) red[w] = mx;
    __syncthreads();
    mx = red[0];
    #pragma unroll
    for (int j = 1; j < 8; j++) mx = fmaxf(mx, red[j]);
    __syncthreads();

    float es = 0.0f;
    for (int i = t; i < RRR; i += 256)
        es += __expf(g_a0[i] + g_a1[i] - mx);
    #pragma unroll
    for (int o = 16; o; o >>= 1) es += __shfl_xor_sync(0xffffffffu, es, o);
    if (lane == 0) red[w] = es;
    __syncthreads();
    es = red[0];
    #pragma unroll
    for (int j = 1; j < 8; j++) es += red[j];
    const float inv = 1.0f / es;
    for (int i = t; i < RCH; i += 256)
        cs[i] = __expf(g_a0[r0 + i] + g_a1[r0 + i] - mx) * inv;
    __syncthreads();
}

// ---------------------------------------------------------------------------
// Cross-warp reduce of per-warp partials (a[8] each) + 256 global REDs.
__device__ __forceinline__ void s_reduce_store(const float* a, int b0, int t,
                                               float* sbuf, float scale) {
    __shared__ float sm[8][256];
    const int w = t >> 5, lane = t & 31;
    #pragma unroll
    for (int j = 0; j < 8; j++) sm[w][lane * 8 + j] = a[j];
    __syncthreads();
    float v = sm[0][t];
    #pragma unroll
    for (int ww = 1; ww < 8; ww++) v += sm[ww][t];
    const int b = b0 + (t >> 5);
    const int l = ((t >> 3) & 3) * 8 + (t & 7);
    atomicAdd(&sbuf[b * LL + l], v * scale);
}

// Per-warp streaming accumulate with explicit 6-deep load batches (MLP).
// Warp covers 8-b window, r in [r0 + w*WRD, +WRD). cs==nullptr -> uniform.
__device__ __forceinline__ void s_warp_accum(float* a, const float* cs,
                                             int r0, int b0, int t) {
    const int w = t >> 5, lane = t & 31;
    const int rw = r0 + w * WRD;
    const int b = b0 + (lane >> 2);
    const int4* u = (const int4*)g_uhat + (size_t)rw * 1024 + b * 4 + (lane & 3);

    #pragma unroll
    for (int j = 0; j < 8; j++) a[j] = 0.0f;
    #pragma unroll
    for (int bb = 0; bb < 3; bb++) {
        int4 p[6];
        #pragma unroll
        for (int i = 0; i < 6; i++)
            p[i] = u[(size_t)(bb * 6 + i) * 1024];
        #pragma unroll
        for (int i = 0; i < 6; i++) {
            const float cr = cs ? cs[w * WRD + bb * 6 + i] : 1.0f;
            const __half2* hp = (const __half2*)&p[i];
            #pragma unroll
            for (int j = 0; j < 4; j++) {
                float2 f = __half22float2(hp[j]);
                if (cs) {
                    a[2 * j]     = fmaf(cr, f.x, a[2 * j]);
                    a[2 * j + 1] = fmaf(cr, f.y, a[2 * j + 1]);
                } else {
                    a[2 * j]     += f.x;
                    a[2 * j + 1] += f.y;
                }
            }
        }
    }
}

// it0: c uniform = 1/RRR.
__global__ __launch_bounds__(256, 4) void k_s0() {
    const int t = threadIdx.x;
    float a[8];
    s_warp_accum(a, nullptr, blockIdx.y * RCH, blockIdx.x * 8, t);
    s_reduce_store(a, blockIdx.x * 8, t, g_s0, 1.0f / (float)RRR);
}

// it1: c = softmax(a0)  (g_a1 is zero here)
__global__ __launch_bounds__(256, 4) void k_s1() {
    __shared__ float cs[RCH];
    const int t = threadIdx.x;
    const int r0 = blockIdx.y * RCH;
    block_softmax(cs, r0, t);
    float a[8];
    s_warp_accum(a, cs, r0, blockIdx.x * 8, t);
    s_reduce_store(a, blockIdx.x * 8, t, g_s1, 1.0f);
}

// ---------------------------------------------------------------------------
// a[r] = mean_b sum_l u_hat[r,b,l]*squash(s)[b,l]; 4 r's per block, grid 648.
// Loads batched 4-deep per r for MLP.
template<int IT>
__global__ __launch_bounds__(256, 4) void k_a() {
    __shared__ float vsm[BL];          // squash(s), 32 KB
    __shared__ float red[4][9];
    const int t = threadIdx.x;
    const int w = t >> 5, lane = t & 31;
    const float* sbuf = (IT == 0) ? g_s0 : g_s1;
    float* abuf = (IT == 0) ? g_a0 : g_a1;

    const float4* s4 = (const float4*)sbuf;
    float4* v4 = (float4*)vsm;
    for (int i = t; i < BL / 4; i += 256) {
        float4 s = s4[i];
        float4 o;
        o.x = squashf(s.x); o.y = squashf(s.y);
        o.z = squashf(s.z); o.w = squashf(s.w);
        v4[i] = o;
    }
    __syncthreads();

    const int rbase = blockIdx.x * 4;
    for (int rr = 0; rr < 4; rr++) {
        const int4* u = (const int4*)g_uhat + (size_t)(rbase + rr) * 1024;
        int4 p[4];
        #pragma unroll
        for (int j = 0; j < 4; j++) p[j] = u[j * 256 + t];

        float a[8] = {0.f, 0.f, 0.f, 0.f, 0.f, 0.f, 0.f, 0.f};
        #pragma unroll
        for (int j = 0; j < 4; j++) {
            int idx = j * 256 + t;
            const __half2* hp = (const __half2*)&p[j];
            float4 va = v4[idx * 2];
            float4 vb = v4[idx * 2 + 1];
            float2 f0 = __half22float2(hp[0]);
            float2 f1 = __half22float2(hp[1]);
            float2 f2 = __half22float2(hp[2]);
            float2 f3 = __half22float2(hp[3]);
            a[0] = fmaf(f0.x, va.x, a[0]);  a[1] = fmaf(f0.y, va.y, a[1]);
            a[2] = fmaf(f1.x, va.z, a[2]);  a[3] = fmaf(f1.y, va.w, a[3]);
            a[4] = fmaf(f2.x, vb.x, a[4]);  a[5] = fmaf(f2.y, vb.y, a[5]);
            a[6] = fmaf(f3.x, vb.z, a[6]);  a[7] = fmaf(f3.y, vb.w, a[7]);
        }
        float s = ((a[0] + a[1]) + (a[2] + a[3])) + ((a[4] + a[5]) + (a[6] + a[7]));
        #pragma unroll
        for (int o = 16; o; o >>= 1) s += __shfl_xor_sync(0xffffffffu, s, o);
        if (lane == 0) red[rr][w] = s;
    }
    __syncthreads();
    if (t < 32) {
        int rr = t >> 3, ww = t & 7;
        float v = red[rr][ww];
        v += __shfl_xor_sync(0xffffffffu, v, 1);
        v += __shfl_xor_sync(0xffffffffu, v, 2);
        v += __shfl_xor_sync(0xffffffffu, v, 4);
        if (ww == 0) abuf[rbase + rr] = v * (1.0f / (float)BB);
    }
}

// ---------------------------------------------------------------------------
// Final iteration fused: c2 = softmax(a0+a1); writes u_out = c2[r]*u_hat and
// accumulates s2 via smem reduction + 256 REDs. 6-deep load batches.
__global__ __launch_bounds__(256, 4) void k_s_out(float* __restrict__ out) {
    __shared__ float cs[RCH];
    const int t = threadIdx.x;
    const int r0 = blockIdx.y * RCH;
    const int b0 = blockIdx.x * 8;
    block_softmax(cs, r0, t);

    const int w = t >> 5, lane = t & 31;
    const int rw = r0 + w * WRD;
    const int b = b0 + (lane >> 2);
    const int l8 = (lane & 3) * 8;
    const int4* u = (const int4*)g_uhat + (size_t)rw * 1024 + b * 4 + (lane & 3);
    float* uo = out + BL + b * RL + l8;

    float a[8] = {0.f, 0.f, 0.f, 0.f, 0.f, 0.f, 0.f, 0.f};
    #pragma unroll
    for (int bb = 0; bb < 3; bb++) {
        int4 p[6];
        #pragma unroll
        for (int i = 0; i < 6; i++)
            p[i] = u[(size_t)(bb * 6 + i) * 1024];
        #pragma unroll
        for (int i = 0; i < 6; i++) {
            const int ri = bb * 6 + i;
            const float cr = cs[w * WRD + ri];
            const __half2* hp = (const __half2*)&p[i];
            float2 f0 = __half22float2(hp[0]);
            float2 f1 = __half22float2(hp[1]);
            float2 f2 = __half22float2(hp[2]);
            float2 f3 = __half22float2(hp[3]);
            float4 o1, o2;
            o1.x = cr * f0.x;  o1.y = cr * f0.y;
            o1.z = cr * f1.x;  o1.w = cr * f1.y;
            o2.x = cr * f2.x;  o2.y = cr * f2.y;
            o2.z = cr * f3.x;  o2.w = cr * f3.y;
            a[0] += o1.x; a[1] += o1.y; a[2] += o1.z; a[3] += o1.w;
            a[4] += o2.x; a[5] += o2.y; a[6] += o2.z; a[7] += o2.w;
            float* dst = uo + (rw + ri) * LL;
            ((float4*)dst)[0] = o1;
            ((float4*)dst)[1] = o2;
        }
    }
    s_reduce_store(a, b0, t, g_s2, 1.0f);
}

// ---------------------------------------------------------------------------
// v_out = squash(s2) into out[0:8192].
__global__ __launch_bounds__(256) void k_vout(float* __restrict__ out) {
    int i = blockIdx.x * 256 + threadIdx.x;
    out[i] = squashf(g_s2[i]);
}

// ---------------------------------------------------------------------------
extern "C" void kernel_launch(void* const* d_in, const int* in_sizes, int n_in,
                              void* d_out, int out_size) {
    const float* x = (const float*)d_in[0];   // (B, R, C)
    const float* W = (const float*)d_in[1];   // (1, R, 1, L, C)
    float* out = (float*)d_out;

    k_uhat<<<RRR, 256>>>(x, W);                // + scratch init
    k_s0<<<dim3(32, GYS), 256>>>();            // it 0 (uniform c)
    k_a<0><<<648, 256>>>();                    // a0
    k_s1<<<dim3(32, GYS), 256>>>();            // it 1
    k_a<1><<<648, 256>>>();                    // a1
    k_s_out<<<dim3(32, GYS), 256>>>(out);      // it 2 + u_out
    k_vout<<<32, 256>>>(out);                  // v_out
}